// round 16
// baseline (speedup 1.0000x reference)
#include <cuda_runtime.h>
#include <float.h>

#define V    23
#define Hdim 256
#define Lseq 1024
#define TPB  128   // 4 warps, one chain (batch element) per CTA

// ---- Blackwell packed fp32x2 FMA (PTX-only; doubles fp32 throughput) ----
__device__ __forceinline__ unsigned long long ffma2(unsigned long long a,
                                                    unsigned long long b,
                                                    unsigned long long c) {
    unsigned long long d;
    asm("fma.rn.f32x2 %0, %1, %2, %3;" : "=l"(d) : "l"(a), "l"(b), "l"(c));
    return d;
}
__device__ __forceinline__ unsigned long long pack2(float x, float y) {
    unsigned long long d;
    asm("mov.b64 %0, {%1, %2};" : "=l"(d) : "f"(x), "f"(y));
    return d;
}
__device__ __forceinline__ float2 unpack2(unsigned long long a) {
    float2 r;
    asm("mov.b64 {%0, %1}, %2;" : "=f"(r.x), "=f"(r.y) : "l"(a));
    return r;
}

// Monotonic float->uint key, branchless: preserves float ordering
__device__ __forceinline__ unsigned fkey(float f) {
    unsigned u = __float_as_uint(f);
    return u ^ ((unsigned)(((int)u) >> 31) | 0x80000000u);
}

// Merge-reduce with selects (only the final mask-4/mask-2 rounds need them)
#define MRG(lo, hi, bit) do {                                   \
    float _keep = (lane & (bit)) ? (hi) : (lo);                 \
    float _send = (lane & (bit)) ? (lo) : (hi);                 \
    (lo) = _keep + __shfl_xor_sync(0xffffffffu, _send, (bit));  \
} while (0)

// mod-inverse table mod 23, 5 bits per entry, in two u64 constants
// s = 0..11 -> INV_LO, s = 12..22 -> INV_HI
#define INV_LO ( 0ull | (1ull<<5) | (12ull<<10) | (8ull<<15) | (6ull<<20) | \
                (14ull<<25) | (4ull<<30) | (10ull<<35) | (3ull<<40) |      \
                (18ull<<45) | (7ull<<50) | (21ull<<55) )
#define INV_HI ( 2ull | (16ull<<5) | (5ull<<10) | (20ull<<15) | (13ull<<20) | \
                (19ull<<25) | (9ull<<30) | (17ull<<35) | (15ull<<40) |       \
                (11ull<<45) | (22ull<<50) )

__global__ __launch_bounds__(TPB, 4)
void daf_kernel(const int* __restrict__ x_tokens,
                const float* __restrict__ W1,
                const float* __restrict__ b1,
                const float* __restrict__ W2,
                const float* __restrict__ b2,
                float* __restrict__ out)
{
    __shared__ __align__(16) float sW1[V * Hdim];       // 23552 B, row y contiguous
    __shared__ __align__(16) unsigned long long pm[2][4]; // per-warp (key<<32 | 31-idx)
    __shared__ int stok[Lseq];                          // this chain's input tokens

    const int tid  = threadIdx.x;
    const int b    = blockIdx.x;
    const int lane = tid & 31;
    const int warp = tid >> 5;

    // Output-group repartition: each warp's 12 logits lie in ONE argmax group.
    // warp0: loc[0..11], warp1: loc[12..22], warp2: sc[0..11], warp3: sc[12..22]
    const int g    = warp >> 1;        // 0 = loc group, 1 = scale group
    const int base = (warp & 1) * 12;  // within-group offset (warps 1,3: 11 valid + 1 pad)

    // ---- one-time setup ----
    for (int i = tid; i < V * Hdim; i += TPB) sW1[i] = W1[i];
    {
        const int* tokrow = x_tokens + (size_t)b * Lseq;
        for (int i = tid; i < Lseq; i += TPB) stok[i] = tokrow[i];
    }

    // Per-lane h-row ownership: j_m = (m<4) ? 4*lane+m : 128 + 4*lane + (m-4)
    int jidx[8];
    #pragma unroll
    for (int m = 0; m < 8; ++m)
        jidx[m] = (m < 4) ? (4 * lane + m) : (124 + 4 * lane + m);

    // W2 in registers with the select-free tree permutation baked in:
    // scalar accumulator k (k=6a+3b+c) on this lane holds logical within-warp
    // output q(k) = 6*(a^b4) + 3*(b^b3) + c  (b3/b4 = lane bits 3/4).
    // W2 column for within-warp output q:  col = g*23 + base + q  (pad -> 0).
    const int lb3 = (lane >> 3) & 1;
    const int lb4 = (lane >> 4) & 1;
    unsigned long long w2p[6][8];
    #pragma unroll
    for (int p = 0; p < 6; ++p) {
        int k0 = 2 * p, k1 = 2 * p + 1;
        int q0 = 6 * ((k0 / 6) ^ lb4) + 3 * (((k0 % 6) / 3) ^ lb3) + (k0 % 3);
        int q1 = 6 * ((k1 / 6) ^ lb4) + 3 * (((k1 % 6) / 3) ^ lb3) + (k1 % 3);
        int i0 = base + q0, i1 = base + q1;        // index within group (0..22 valid)
        int o0 = g * V + i0, o1 = g * V + i1;      // W2 column
        #pragma unroll
        for (int m = 0; m < 8; ++m) {
            const float* row = W2 + jidx[m] * (2 * V);
            float v0 = (i0 < V) ? row[o0] : 0.0f;
            float v1 = (i1 < V) ? row[o1] : 0.0f;
            w2p[p][m] = pack2(v0, v1);
        }
    }

    // after the tree, r0 on this lane holds within-warp output q_loc:
    const int b1b = (lane >> 1) & 1, b2b = (lane >> 2) & 1;
    const int q_loc = b1b ? (2 + 3 * lb3 + 6 * lb4) : (b2b + 3 * lb3 + 6 * lb4);
    const int i_gr  = base + q_loc;               // index within argmax group
    const bool vld  = (i_gr < V);
    const float rbias = vld ? b2[g * V + i_gr] : 0.0f;

    // hpre replicated per warp, in registers. acc0 = 0 -> hpre = b1.
    float hp8[8];
    #pragma unroll
    for (int m = 0; m < 8; ++m) hp8[m] = b1[jidx[m]];

    float* op = out + (size_t)b * Lseq * V;

    __syncthreads();

    for (int t = 0; t < Lseq; ++t) {
        const int tok = stok[t];     // hoisted: LDS latency hidden under matvec

        // 1) matvec: each warp has ALL of h in registers (relu on the fly)
        unsigned long long a0 = 0, a1 = 0, a2 = 0, a3 = 0, a4 = 0, a5 = 0;
        #pragma unroll
        for (int m = 0; m < 8; ++m) {
            float hv = fmaxf(hp8[m], 0.0f);
            unsigned long long hp = pack2(hv, hv);
            a0 = ffma2(hp, w2p[0][m], a0);
            a1 = ffma2(hp, w2p[1][m], a1);
            a2 = ffma2(hp, w2p[2][m], a2);
            a3 = ffma2(hp, w2p[3][m], a3);
            a4 = ffma2(hp, w2p[4][m], a4);
            a5 = ffma2(hp, w2p[5][m], a5);
        }
        float2 q0 = unpack2(a0), q1 = unpack2(a1), q2 = unpack2(a2);
        float2 q3 = unpack2(a3), q4 = unpack2(a4), q5 = unpack2(a5);
        float r0 = q0.x, r1 = q0.y, r2  = q1.x, r3  = q1.y, r4  = q2.x, r5  = q2.y;
        float r6 = q3.x, r7 = q3.y, r8  = q4.x, r9  = q4.y, r10 = q5.x, r11 = q5.y;

        // 2) reduction tree (mask-16/8 select-free via permuted W2 loads)
        r0 += __shfl_xor_sync(0xffffffffu, r6,  16);
        r1 += __shfl_xor_sync(0xffffffffu, r7,  16);
        r2 += __shfl_xor_sync(0xffffffffu, r8,  16);
        r3 += __shfl_xor_sync(0xffffffffu, r9,  16);
        r4 += __shfl_xor_sync(0xffffffffu, r10, 16);
        r5 += __shfl_xor_sync(0xffffffffu, r11, 16);
        r0 += __shfl_xor_sync(0xffffffffu, r3,  8);
        r1 += __shfl_xor_sync(0xffffffffu, r4,  8);
        r2 += __shfl_xor_sync(0xffffffffu, r5,  8);
        MRG(r0, r1, 4);
        r2 += __shfl_xor_sync(0xffffffffu, r2, 4);
        MRG(r0, r2, 2);
        r0 += __shfl_xor_sync(0xffffffffu, r0, 1);

        // 3) PRE-BAR argmax: value redux-max, then ballot+ffs to find the
        //    winning lane; its group index follows from the lane-bit formula.
        //    (Distinct outputs have distinct fp32 dot products; winning lanes
        //    are the duplicates of one output.)
        unsigned key  = vld ? fkey(r0 + rbias) : 0u;
        unsigned km   = __reduce_max_sync(0xffffffffu, key);
        unsigned ball = __ballot_sync(0xffffffffu, key == km);
        int lw = __ffs(ball) - 1;            // a winning lane
        int qw = (((lw >> 1) & 1) ? 2 : ((lw >> 2) & 1))
                 + 3 * ((lw >> 3) & 1) + 6 * ((lw >> 4) & 1);
        int iw = base + qw;                  // winning index within group
        if (lane == 0)
            pm[t & 1][warp] = ((unsigned long long)km << 32) | (unsigned)(31 - iw);
        __syncthreads();           // the ONLY barrier per step

        // 4) post-bar: u64 max picks (max key, then min index); warp0/2 hold
        //    smaller indices, so ties across warps also resolve first-index.
        const ulonglong2 p01 = *reinterpret_cast<const ulonglong2*>(&pm[t & 1][0]);
        const ulonglong2 p23 = *reinterpret_cast<const ulonglong2*>(&pm[t & 1][2]);
        unsigned long long kl = (p01.x >= p01.y) ? p01.x : p01.y;
        unsigned long long ks = (p23.x >= p23.y) ? p23.x : p23.y;
        int loc = 31 - (int)(kl & 31u);
        int sc  = 31 - (int)(ks & 31u);

        // 5) token arithmetic, ALU-only (no table lookups)
        int md = tok - loc;
        md += (md >> 31) & V;                       // (a0 - loc) mod 23
        unsigned inv = (unsigned)(((sc < 12) ? (INV_LO >> (5 * sc))
                                             : (INV_HI >> (5 * (sc - 12)))) & 31ull);
        int mprod = (int)inv * md;                  // <= 22*22 = 484
        int y = mprod - V * ((mprod * 5699) >> 17); // exact (inv*md) % 23

        // 6) one-hot output row (warp 3 only; covers whole poisoned buffer)
        if (warp == 3 && lane < V) op[lane] = (lane == y) ? 1.0f : 0.0f;
        op += V;

        // 7) per-warp state update: hpre += W1[y, :]
        const float4 wa = *reinterpret_cast<const float4*>(&sW1[y * Hdim + 4 * lane]);
        const float4 wb = *reinterpret_cast<const float4*>(&sW1[y * Hdim + 128 + 4 * lane]);
        hp8[0] += wa.x; hp8[1] += wa.y; hp8[2] += wa.z; hp8[3] += wa.w;
        hp8[4] += wb.x; hp8[5] += wb.y; hp8[6] += wb.z; hp8[7] += wb.w;
    }
}

extern "C" void kernel_launch(void* const* d_in, const int* in_sizes, int n_in,
                              void* d_out, int out_size) {
    const int*   x  = (const int*)d_in[0];
    const float* W1 = (const float*)d_in[1];
    const float* b1 = (const float*)d_in[2];
    const float* W2 = (const float*)d_in[3];
    const float* b2 = (const float*)d_in[4];
    int Bn = in_sizes[0] / Lseq;   // 512
    daf_kernel<<<Bn, TPB>>>(x, W1, b1, W2, b2, (float*)d_out);
}

// round 17
// speedup vs baseline: 1.3525x; 1.3525x over previous
#include <cuda_runtime.h>
#include <float.h>

#define V    23
#define Hdim 256
#define Lseq 1024
#define TPB  64    // 2 warps = ONE chain; warp0 -> loc logits, warp1 -> scale logits

// ---- Blackwell packed fp32x2 FMA (PTX-only; doubles fp32 throughput) ----
__device__ __forceinline__ unsigned long long ffma2(unsigned long long a,
                                                    unsigned long long b,
                                                    unsigned long long c) {
    unsigned long long d;
    asm("fma.rn.f32x2 %0, %1, %2, %3;" : "=l"(d) : "l"(a), "l"(b), "l"(c));
    return d;
}
__device__ __forceinline__ unsigned long long pack2(float x, float y) {
    unsigned long long d;
    asm("mov.b64 %0, {%1, %2};" : "=l"(d) : "f"(x), "f"(y));
    return d;
}
__device__ __forceinline__ float2 unpack2(unsigned long long a) {
    float2 r;
    asm("mov.b64 {%0, %1}, %2;" : "=f"(r.x), "=f"(r.y) : "l"(a));
    return r;
}

// Monotonic float->uint key, branchless: preserves float ordering
__device__ __forceinline__ unsigned fkey(float f) {
    unsigned u = __float_as_uint(f);
    return u ^ ((unsigned)(((int)u) >> 31) | 0x80000000u);
}

// Merge-reduce with selects (only the final mask-2/mask-1 rounds need them)
#define MRG(lo, hi, bit) do {                                   \
    float _keep = (lane & (bit)) ? (hi) : (lo);                 \
    float _send = (lane & (bit)) ? (lo) : (hi);                 \
    (lo) = _keep + __shfl_xor_sync(0xffffffffu, _send, (bit));  \
} while (0)

// mod-inverse table mod 23, 5 bits per entry, in two u64 constants
#define INV_LO ( 0ull | (1ull<<5) | (12ull<<10) | (8ull<<15) | (6ull<<20) | \
                (14ull<<25) | (4ull<<30) | (10ull<<35) | (3ull<<40) |      \
                (18ull<<45) | (7ull<<50) | (21ull<<55) )
#define INV_HI ( 2ull | (16ull<<5) | (5ull<<10) | (20ull<<15) | (13ull<<20) | \
                (19ull<<25) | (9ull<<30) | (17ull<<35) | (15ull<<40) |       \
                (11ull<<45) | (22ull<<50) )

__global__ __launch_bounds__(TPB, 4)
void daf_kernel(const int* __restrict__ x_tokens,
                const float* __restrict__ W1,
                const float* __restrict__ b1,
                const float* __restrict__ W2,
                const float* __restrict__ b2,
                float* __restrict__ out)
{
    __shared__ __align__(16) float sW1[V * Hdim];  // 23552 B, row y contiguous
    __shared__ unsigned sx[2][2];                  // [buf][warp] argmax exchange
    __shared__ int stok[Lseq];                     // this chain's input tokens

    const int tid  = threadIdx.x;
    const int b    = blockIdx.x;
    const int lane = tid & 31;
    const int g    = tid >> 5;       // 0 = loc warp, 1 = scale warp

    // ---- one-time setup ----
    for (int i = tid; i < V * Hdim; i += TPB) sW1[i] = W1[i];
    {
        const int* tokrow = x_tokens + (size_t)b * Lseq;
        for (int i = tid; i < Lseq; i += TPB) stok[i] = tokrow[i];
    }

    // Per-lane h-row ownership: j_m = (m<4) ? 4*lane+m : 128 + 4*lane + (m-4)
    int jidx[8];
    #pragma unroll
    for (int m = 0; m < 8; ++m)
        jidx[m] = (m < 4) ? (4 * lane + m) : (124 + 4 * lane + m);

    // W2 in registers, select-free tree permutation over 24 slots:
    // scalar slot k (k=0..23) on this lane holds logical group output
    //   q(k) = 12*((k/12)^lb4) + 6*(((k/6)&1)^lb3) + 3*(((k/3)&1)^lb2) + k%3
    // so reduction rounds 16/8/4 pair slots (k,k+12)/(k,k+6)/(k,k+3) with
    // plain add+shuffle. q==23 is the single pad slot (-> zero weights).
    const int lb2 = (lane >> 2) & 1;
    const int lb3 = (lane >> 3) & 1;
    const int lb4 = (lane >> 4) & 1;
    unsigned long long w2p[12][8];
    #pragma unroll
    for (int p = 0; p < 12; ++p) {
        int k0 = 2 * p, k1 = 2 * p + 1;
        int q0 = 12 * ((k0 / 12) ^ lb4) + 6 * (((k0 / 6) & 1) ^ lb3)
               + 3 * (((k0 / 3) & 1) ^ lb2) + (k0 % 3);
        int q1 = 12 * ((k1 / 12) ^ lb4) + 6 * (((k1 / 6) & 1) ^ lb3)
               + 3 * (((k1 / 3) & 1) ^ lb2) + (k1 % 3);
        int o0 = g * V + q0, o1 = g * V + q1;      // W2 column (q<23 valid)
        #pragma unroll
        for (int m = 0; m < 8; ++m) {
            const float* row = W2 + jidx[m] * (2 * V);
            float v0 = (q0 < V) ? row[o0] : 0.0f;
            float v1 = (q1 < V) ? row[o1] : 0.0f;
            w2p[p][m] = pack2(v0, v1);
        }
    }

    // final-lane -> group index after the full tree:
    //   i(lane) = 12*lb4 + 6*lb3 + 3*lb2 + (bit0 ? 2 : (bit1 ? 1 : 0))
    const int c3   = (lane & 1) ? 2 : ((lane >> 1) & 1);
    const int i_gr = 12 * lb4 + 6 * lb3 + 3 * lb2 + c3;
    const bool vld = (i_gr < V);
    const float rbias = vld ? b2[g * V + i_gr] : 0.0f;

    // hpre replicated per warp, in registers. acc0 = 0 -> hpre = b1.
    float hp8[8];
    #pragma unroll
    for (int m = 0; m < 8; ++m) hp8[m] = b1[jidx[m]];

    float* op = out + (size_t)b * Lseq * V;

    __syncthreads();

    for (int t = 0; t < Lseq; ++t) {
        const int tok = stok[t];     // hoisted: LDS latency hidden under matvec

        // 1) matvec: this warp computes ALL 23 logits of its group
        unsigned long long acc[12];
        #pragma unroll
        for (int p = 0; p < 12; ++p) acc[p] = 0ull;
        #pragma unroll
        for (int m = 0; m < 8; ++m) {
            float hv = fmaxf(hp8[m], 0.0f);
            unsigned long long hp = pack2(hv, hv);
            #pragma unroll
            for (int p = 0; p < 12; ++p) acc[p] = ffma2(hp, w2p[p][m], acc[p]);
        }
        float s[24];
        #pragma unroll
        for (int p = 0; p < 12; ++p) {
            float2 q = unpack2(acc[p]);
            s[2 * p] = q.x; s[2 * p + 1] = q.y;
        }

        // 2) reduction tree: rounds 16/8/4 select-free (permuted W2 loads)
        #pragma unroll
        for (int k = 0; k < 12; ++k) s[k] += __shfl_xor_sync(0xffffffffu, s[k + 12], 16);
        #pragma unroll
        for (int k = 0; k < 6; ++k)  s[k] += __shfl_xor_sync(0xffffffffu, s[k + 6], 8);
        #pragma unroll
        for (int k = 0; k < 3; ++k)  s[k] += __shfl_xor_sync(0xffffffffu, s[k + 3], 4);
        MRG(s[0], s[1], 2);
        s[2] += __shfl_xor_sync(0xffffffffu, s[2], 2);
        MRG(s[0], s[2], 1);

        // 3) IN-WARP argmax (complete — no cross-warp combining needed)
        unsigned key  = vld ? fkey(s[0] + rbias) : 0u;
        unsigned km   = __reduce_max_sync(0xffffffffu, key);
        unsigned ball = __ballot_sync(0xffffffffu, key == km);
        int lw = __ffs(ball) - 1;
        int iw = 12 * ((lw >> 4) & 1) + 6 * ((lw >> 3) & 1) + 3 * ((lw >> 2) & 1)
               + ((lw & 1) ? 2 : ((lw >> 1) & 1));

        // 4) exchange loc <-> sc across the 2-warp CTA (tiny barrier)
        if (lane == 0) sx[t & 1][g] = (unsigned)iw;
        __syncthreads();             // 2 warps only
        int other = (int)sx[t & 1][1 - g];
        int loc = g ? other : iw;
        int sc  = g ? iw    : other;

        // 5) token arithmetic, ALU-only
        int md = tok - loc;
        md += (md >> 31) & V;                       // (a0 - loc) mod 23
        unsigned inv = (unsigned)(((sc < 12) ? (INV_LO >> (5 * sc))
                                             : (INV_HI >> (5 * (sc - 12)))) & 31ull);
        int mprod = (int)inv * md;                  // <= 22*22 = 484
        int y = mprod - V * ((mprod * 5699) >> 17); // exact (inv*md) % 23

        // 6) one-hot output row (warp 1 writes)
        if (g == 1 && lane < V) op[lane] = (lane == y) ? 1.0f : 0.0f;
        op += V;

        // 7) per-warp state update: hpre += W1[y, :]
        const float4 wa = *reinterpret_cast<const float4*>(&sW1[y * Hdim + 4 * lane]);
        const float4 wb = *reinterpret_cast<const float4*>(&sW1[y * Hdim + 128 + 4 * lane]);
        hp8[0] += wa.x; hp8[1] += wa.y; hp8[2] += wa.z; hp8[3] += wa.w;
        hp8[4] += wb.x; hp8[5] += wb.y; hp8[6] += wb.z; hp8[7] += wb.w;
    }
}

extern "C" void kernel_launch(void* const* d_in, const int* in_sizes, int n_in,
                              void* d_out, int out_size) {
    const int*   x  = (const int*)d_in[0];
    const float* W1 = (const float*)d_in[1];
    const float* b1 = (const float*)d_in[2];
    const float* W2 = (const float*)d_in[3];
    const float* b2 = (const float*)d_in[4];
    int Bn = in_sizes[0] / Lseq;   // 512
    daf_kernel<<<Bn, TPB>>>(x, W1, b1, W2, b2, (float*)d_out);
}